// round 10
// baseline (speedup 1.0000x reference)
#include <cuda_runtime.h>
#include <math.h>
#include <limits.h>

#define EPSV 1e-12f
#define DIMS 768
#define MAXM (131072)
#define KMAX 8
#define TPB 256
#define WPB (TPB / 32)

// Scratch (no cudaMalloc allowed)
__device__ float g_scores[MAXM];
__device__ unsigned int g_done = 0;   // last-block-done counter (reset each run)

// Ordering consistent with jax.lax.top_k: higher value first, lower index on ties.
__device__ __forceinline__ bool better(float v1, int i1, float v2, int i2) {
    return (v1 > v2) || (v1 == v2 && i1 < i2);
}

// Branchless sorted-insert into a register-resident descending top-K list.
// All indices compile-time -> stays in registers (no LDL/STL on hot path).
template<int K>
__device__ __forceinline__ void insertK(float (&lv)[K], int (&li)[K], float v, int i) {
    if (!better(v, i, lv[K - 1], li[K - 1])) return;
    bool b[K];
    #pragma unroll
    for (int j = 0; j < K; j++) b[j] = better(lv[j], li[j], v, i);
    #pragma unroll
    for (int j = K - 1; j >= 1; --j) {
        lv[j] = b[j] ? lv[j] : (b[j - 1] ? v : lv[j - 1]);
        li[j] = b[j] ? li[j] : (b[j - 1] ? i : li[j - 1]);
    }
    if (!b[0]) { lv[0] = v; li[0] = i; }
}

// Full-warp merge: after this, EVERY lane holds the warp's merged top-K.
template<int K>
__device__ __forceinline__ void warpMergeK(float (&lv)[K], int (&li)[K]) {
    #pragma unroll
    for (int o = 16; o; o >>= 1) {
        float pv[K];
        int   pi[K];
        #pragma unroll
        for (int j = 0; j < K; j++) {
            pv[j] = __shfl_xor_sync(0xffffffffu, lv[j], o);
            pi[j] = __shfl_xor_sync(0xffffffffu, li[j], o);
        }
        #pragma unroll
        for (int j = 0; j < K; j++) insertK<K>(lv, li, pv[j], pi[j]);
    }
}

// ---------------------------------------------------------------------------
// Single fused kernel: scoring (one warp per row, proven hot path) + top-k
// done by the LAST block to finish (threadfence-reduction pattern).
// ---------------------------------------------------------------------------
template<int K>
__global__ void __launch_bounds__(TPB)
score_topk_fused(const float4* __restrict__ q4,
                 const float*  __restrict__ loc,
                 const float4* __restrict__ feats4,
                 const float2* __restrict__ locs2,
                 const float4* __restrict__ meta4,
                 int M, float* __restrict__ out)
{
    __shared__ float s_wval[WPB * K];
    __shared__ int   s_widx[WPB * K];
    __shared__ bool  s_last;

    const int wid  = threadIdx.x >> 5;
    const int lane = threadIdx.x & 31;
    const int row  = blockIdx.x * WPB + wid;

    // ================= scoring phase (unchanged hot path) =================
    if (row < M) {
        float2 lrow = make_float2(0.f, 0.f);
        float4 mrow = make_float4(0.f, 0.f, 0.f, 0.f);
        float  l0 = 0.f, l1 = 0.f;
        if (lane == 0) {
            lrow = __ldg(locs2 + row);
            mrow = __ldg(meta4 + row);
            l0 = __ldg(loc);
            l1 = __ldg(loc + 1);
        }

        const float4* __restrict__ rp = feats4 + (size_t)row * (DIMS / 4);

        float4 a0 = __ldcs(rp + lane + 32 * 0);
        float4 a1 = __ldcs(rp + lane + 32 * 1);
        float4 a2 = __ldcs(rp + lane + 32 * 2);
        float4 a3 = __ldcs(rp + lane + 32 * 3);
        float4 a4 = __ldcs(rp + lane + 32 * 4);
        float4 a5 = __ldcs(rp + lane + 32 * 5);

        float dot = 0.f, ss = 0.f, qq = 0.f;
        {
            float4 b;
            b = __ldg(q4 + lane + 32 * 0);
            dot += a0.x*b.x + a0.y*b.y + a0.z*b.z + a0.w*b.w;
            ss  += a0.x*a0.x + a0.y*a0.y + a0.z*a0.z + a0.w*a0.w;
            qq  += b.x*b.x + b.y*b.y + b.z*b.z + b.w*b.w;
            b = __ldg(q4 + lane + 32 * 1);
            dot += a1.x*b.x + a1.y*b.y + a1.z*b.z + a1.w*b.w;
            ss  += a1.x*a1.x + a1.y*a1.y + a1.z*a1.z + a1.w*a1.w;
            qq  += b.x*b.x + b.y*b.y + b.z*b.z + b.w*b.w;
            b = __ldg(q4 + lane + 32 * 2);
            dot += a2.x*b.x + a2.y*b.y + a2.z*b.z + a2.w*b.w;
            ss  += a2.x*a2.x + a2.y*a2.y + a2.z*a2.z + a2.w*a2.w;
            qq  += b.x*b.x + b.y*b.y + b.z*b.z + b.w*b.w;
            b = __ldg(q4 + lane + 32 * 3);
            dot += a3.x*b.x + a3.y*b.y + a3.z*b.z + a3.w*b.w;
            ss  += a3.x*a3.x + a3.y*a3.y + a3.z*a3.z + a3.w*a3.w;
            qq  += b.x*b.x + b.y*b.y + b.z*b.z + b.w*b.w;
            b = __ldg(q4 + lane + 32 * 4);
            dot += a4.x*b.x + a4.y*b.y + a4.z*b.z + a4.w*b.w;
            ss  += a4.x*a4.x + a4.y*a4.y + a4.z*a4.z + a4.w*a4.w;
            qq  += b.x*b.x + b.y*b.y + b.z*b.z + b.w*b.w;
            b = __ldg(q4 + lane + 32 * 5);
            dot += a5.x*b.x + a5.y*b.y + a5.z*b.z + a5.w*b.w;
            ss  += a5.x*a5.x + a5.y*a5.y + a5.z*a5.z + a5.w*a5.w;
            qq  += b.x*b.x + b.y*b.y + b.z*b.z + b.w*b.w;
        }

        #pragma unroll
        for (int o = 16; o; o >>= 1) {
            dot += __shfl_xor_sync(0xffffffffu, dot, o);
            ss  += __shfl_xor_sync(0xffffffffu, ss,  o);
            qq  += __shfl_xor_sync(0xffffffffu, qq,  o);
        }

        if (lane == 0) {
            float qn = fmaxf(sqrtf(qq), EPSV);
            float mn = fmaxf(sqrtf(ss), EPSV);
            float sim = dot / (mn * qn);

            float dx = lrow.x - l0;
            float dy = lrow.y - l1;
            float spatial = 1.f / (1.f + sqrtf(dx * dx + dy * dy));

            // exp(-(3600 - ts)/3600) == exp(ts/3600 - 1)
            float temporal = expf(mrow.y * (1.f / 3600.f) - 1.f);

            g_scores[row] = (0.5f * sim + 0.3f * spatial + 0.2f * temporal) * mrow.x;
        }
    }

    // ================= last-block election =================
    __syncthreads();                      // all warps' score stores issued
    if (threadIdx.x == 0) {
        __threadfence();                  // publish this block's scores
        unsigned int t = atomicAdd(&g_done, 1u);
        s_last = (t == (unsigned int)(gridDim.x - 1));
    }
    __syncthreads();
    if (!s_last) return;
    __threadfence();                      // acquire: see all blocks' scores

    // ================= top-k by the one surviving block =================
    float lv[K];
    int   li[K];
    #pragma unroll
    for (int j = 0; j < K; j++) { lv[j] = -INFINITY; li[j] = INT_MAX; }

    const float4* sc4 = (const float4*)g_scores;
    const int n4 = M >> 2;
    for (int i = threadIdx.x; i < n4; i += TPB) {
        // L2 read (L1 may be stale for other SMs' writes)
        float4 v;
        v.x = __ldcg(&g_scores[4 * i + 0]);
        v.y = __ldcg(&g_scores[4 * i + 1]);
        v.z = __ldcg(&g_scores[4 * i + 2]);
        v.w = __ldcg(&g_scores[4 * i + 3]);
        const int base = 4 * i;
        insertK<K>(lv, li, v.x, base + 0);
        insertK<K>(lv, li, v.y, base + 1);
        insertK<K>(lv, li, v.z, base + 2);
        insertK<K>(lv, li, v.w, base + 3);
    }
    {
        int i = (n4 << 2) + threadIdx.x;  // M % 4 remainder
        if (i < M) insertK<K>(lv, li, __ldcg(&g_scores[i]), i);
    }

    warpMergeK<K>(lv, li);
    if (lane == 0) {
        #pragma unroll
        for (int j = 0; j < K; j++) {
            s_wval[wid * K + j] = lv[j];
            s_widx[wid * K + j] = li[j];
        }
    }
    __syncthreads();

    if (wid == 0) {
        float mv[K];
        int   mi[K];
        #pragma unroll
        for (int j = 0; j < K; j++) { mv[j] = -INFINITY; mi[j] = INT_MAX; }
        if (lane < WPB) {
            #pragma unroll
            for (int j = 0; j < K; j++) { mv[j] = s_wval[lane * K + j]; mi[j] = s_widx[lane * K + j]; }
        }
        warpMergeK<K>(mv, mi);
        if (lane == 0) {
            #pragma unroll
            for (int j = 0; j < K; j++) {
                out[j]     = mv[j];          // top_scores (sorted desc, ties by index)
                out[K + j] = (float)mi[j];   // top_indices (exact in fp32 for idx < 2^24)
            }
            g_done = 0;                      // reset for next graph replay
        }
    }
}

// ---------------------------------------------------------------------------
// Launch
// ---------------------------------------------------------------------------
extern "C" void kernel_launch(void* const* d_in, const int* in_sizes, int n_in,
                              void* d_out, int out_size)
{
    const float* q     = (const float*)d_in[0];   // (768,)
    const float* loc   = (const float*)d_in[1];   // (2,)
    const float* feats = (const float*)d_in[2];   // (M, 768)
    const float* locs  = (const float*)d_in[3];   // (M, 2)
    const float* meta  = (const float*)d_in[4];   // (M, 4)
    float* out = (float*)d_out;                   // [k scores | k indices]

    int M = in_sizes[2] / DIMS;
    if (M > MAXM) M = MAXM;
    int k = out_size / 2;
    if (k < 1) k = 1;
    if (k > KMAX) k = KMAX;

    const int nblk = (M + WPB - 1) / WPB;

    #define LAUNCH(KK) score_topk_fused<KK><<<nblk, TPB>>>((const float4*)q, loc, \
        (const float4*)feats, (const float2*)locs, (const float4*)meta, M, out)
    switch (k) {
        case 1: LAUNCH(1); break;
        case 2: LAUNCH(2); break;
        case 3: LAUNCH(3); break;
        case 4: LAUNCH(4); break;
        case 5: LAUNCH(5); break;
        case 6: LAUNCH(6); break;
        case 7: LAUNCH(7); break;
        default: LAUNCH(8); break;
    }
    #undef LAUNCH
}

// round 11
// speedup vs baseline: 1.0290x; 1.0290x over previous
#include <cuda_runtime.h>
#include <math.h>
#include <limits.h>

#define EPSV 1e-12f
#define DIMS 768
#define MAXM (131072)
#define KMAX 8
#define TPB 256
#define WPB (TPB / 32)

// Scratch (no cudaMalloc allowed)
__device__ float g_scores[MAXM];
__device__ unsigned int g_done = 0;   // last-block-done counter (reset each run)

// Ordering consistent with jax.lax.top_k: higher value first, lower index on ties.
__device__ __forceinline__ bool better(float v1, int i1, float v2, int i2) {
    return (v1 > v2) || (v1 == v2 && i1 < i2);
}

// Branchless sorted-insert into a register-resident descending top-K list.
template<int K>
__device__ __forceinline__ void insertK(float (&lv)[K], int (&li)[K], float v, int i) {
    if (!better(v, i, lv[K - 1], li[K - 1])) return;
    bool b[K];
    #pragma unroll
    for (int j = 0; j < K; j++) b[j] = better(lv[j], li[j], v, i);
    #pragma unroll
    for (int j = K - 1; j >= 1; --j) {
        lv[j] = b[j] ? lv[j] : (b[j - 1] ? v : lv[j - 1]);
        li[j] = b[j] ? li[j] : (b[j - 1] ? i : li[j - 1]);
    }
    if (!b[0]) { lv[0] = v; li[0] = i; }
}

// Full-warp merge: after this, EVERY lane holds the warp's merged top-K.
template<int K>
__device__ __forceinline__ void warpMergeK(float (&lv)[K], int (&li)[K]) {
    #pragma unroll
    for (int o = 16; o; o >>= 1) {
        float pv[K];
        int   pi[K];
        #pragma unroll
        for (int j = 0; j < K; j++) {
            pv[j] = __shfl_xor_sync(0xffffffffu, lv[j], o);
            pi[j] = __shfl_xor_sync(0xffffffffu, li[j], o);
        }
        #pragma unroll
        for (int j = 0; j < K; j++) insertK<K>(lv, li, pv[j], pi[j]);
    }
}

// Release atomic increment (gpu scope). Orders prior global stores WITHOUT a
// full __threadfence (which on sm_103a emits CCTL.IVALL and flushes L1D —
// the R10 regression). Global stores are write-through to L2, so release
// ordering on the atomic is sufficient for visibility via L2 (.cg reads).
__device__ __forceinline__ unsigned int atomic_inc_release(unsigned int* p) {
    unsigned int old;
    asm volatile("atom.add.release.gpu.u32 %0, [%1], 1;"
                 : "=r"(old) : "l"(p) : "memory");
    return old;
}

// ---------------------------------------------------------------------------
// Single fused kernel: scoring (one warp per row, proven hot path) + top-k
// done by the LAST block to finish.
// ---------------------------------------------------------------------------
template<int K>
__global__ void __launch_bounds__(TPB)
score_topk_fused(const float4* __restrict__ q4,
                 const float*  __restrict__ loc,
                 const float4* __restrict__ feats4,
                 const float2* __restrict__ locs2,
                 const float4* __restrict__ meta4,
                 int M, float* __restrict__ out)
{
    __shared__ float s_wval[WPB * K];
    __shared__ int   s_widx[WPB * K];
    __shared__ bool  s_last;

    const int wid  = threadIdx.x >> 5;
    const int lane = threadIdx.x & 31;
    const int row  = blockIdx.x * WPB + wid;

    // ================= scoring phase (unchanged hot path) =================
    if (row < M) {
        float2 lrow = make_float2(0.f, 0.f);
        float4 mrow = make_float4(0.f, 0.f, 0.f, 0.f);
        float  l0 = 0.f, l1 = 0.f;
        if (lane == 0) {
            lrow = __ldg(locs2 + row);
            mrow = __ldg(meta4 + row);
            l0 = __ldg(loc);
            l1 = __ldg(loc + 1);
        }

        const float4* __restrict__ rp = feats4 + (size_t)row * (DIMS / 4);

        float4 a0 = __ldcs(rp + lane + 32 * 0);
        float4 a1 = __ldcs(rp + lane + 32 * 1);
        float4 a2 = __ldcs(rp + lane + 32 * 2);
        float4 a3 = __ldcs(rp + lane + 32 * 3);
        float4 a4 = __ldcs(rp + lane + 32 * 4);
        float4 a5 = __ldcs(rp + lane + 32 * 5);

        float dot = 0.f, ss = 0.f, qq = 0.f;
        {
            float4 b;
            b = __ldg(q4 + lane + 32 * 0);
            dot += a0.x*b.x + a0.y*b.y + a0.z*b.z + a0.w*b.w;
            ss  += a0.x*a0.x + a0.y*a0.y + a0.z*a0.z + a0.w*a0.w;
            qq  += b.x*b.x + b.y*b.y + b.z*b.z + b.w*b.w;
            b = __ldg(q4 + lane + 32 * 1);
            dot += a1.x*b.x + a1.y*b.y + a1.z*b.z + a1.w*b.w;
            ss  += a1.x*a1.x + a1.y*a1.y + a1.z*a1.z + a1.w*a1.w;
            qq  += b.x*b.x + b.y*b.y + b.z*b.z + b.w*b.w;
            b = __ldg(q4 + lane + 32 * 2);
            dot += a2.x*b.x + a2.y*b.y + a2.z*b.z + a2.w*b.w;
            ss  += a2.x*a2.x + a2.y*a2.y + a2.z*a2.z + a2.w*a2.w;
            qq  += b.x*b.x + b.y*b.y + b.z*b.z + b.w*b.w;
            b = __ldg(q4 + lane + 32 * 3);
            dot += a3.x*b.x + a3.y*b.y + a3.z*b.z + a3.w*b.w;
            ss  += a3.x*a3.x + a3.y*a3.y + a3.z*a3.z + a3.w*a3.w;
            qq  += b.x*b.x + b.y*b.y + b.z*b.z + b.w*b.w;
            b = __ldg(q4 + lane + 32 * 4);
            dot += a4.x*b.x + a4.y*b.y + a4.z*b.z + a4.w*b.w;
            ss  += a4.x*a4.x + a4.y*a4.y + a4.z*a4.z + a4.w*a4.w;
            qq  += b.x*b.x + b.y*b.y + b.z*b.z + b.w*b.w;
            b = __ldg(q4 + lane + 32 * 5);
            dot += a5.x*b.x + a5.y*b.y + a5.z*b.z + a5.w*b.w;
            ss  += a5.x*a5.x + a5.y*a5.y + a5.z*a5.z + a5.w*a5.w;
            qq  += b.x*b.x + b.y*b.y + b.z*b.z + b.w*b.w;
        }

        #pragma unroll
        for (int o = 16; o; o >>= 1) {
            dot += __shfl_xor_sync(0xffffffffu, dot, o);
            ss  += __shfl_xor_sync(0xffffffffu, ss,  o);
            qq  += __shfl_xor_sync(0xffffffffu, qq,  o);
        }

        if (lane == 0) {
            float qn = fmaxf(sqrtf(qq), EPSV);
            float mn = fmaxf(sqrtf(ss), EPSV);
            float sim = dot / (mn * qn);

            float dx = lrow.x - l0;
            float dy = lrow.y - l1;
            float spatial = 1.f / (1.f + sqrtf(dx * dx + dy * dy));

            // exp(-(3600 - ts)/3600) == exp(ts/3600 - 1)
            float temporal = expf(mrow.y * (1.f / 3600.f) - 1.f);

            g_scores[row] = (0.5f * sim + 0.3f * spatial + 0.2f * temporal) * mrow.x;
        }
    }

    // ================= last-block election (flush-free release) =================
    __syncthreads();                      // all warps' score stores issued
    if (threadIdx.x == 0) {
        unsigned int t = atomic_inc_release(&g_done);
        s_last = (t == (unsigned int)(gridDim.x - 1));
    }
    __syncthreads();
    if (!s_last) return;
    __threadfence();                      // acquire (once, last block only)

    // ================= top-k by the one surviving block =================
    float lv[K];
    int   li[K];
    #pragma unroll
    for (int j = 0; j < K; j++) { lv[j] = -INFINITY; li[j] = INT_MAX; }

    const int n4 = M >> 2;
    #pragma unroll 4
    for (int i = threadIdx.x; i < n4; i += TPB) {
        const int base = 4 * i;
        float v0 = __ldcg(&g_scores[base + 0]);   // L2 reads (coherence point)
        float v1 = __ldcg(&g_scores[base + 1]);
        float v2 = __ldcg(&g_scores[base + 2]);
        float v3 = __ldcg(&g_scores[base + 3]);
        insertK<K>(lv, li, v0, base + 0);
        insertK<K>(lv, li, v1, base + 1);
        insertK<K>(lv, li, v2, base + 2);
        insertK<K>(lv, li, v3, base + 3);
    }
    {
        int i = (n4 << 2) + threadIdx.x;  // M % 4 remainder
        if (i < M) insertK<K>(lv, li, __ldcg(&g_scores[i]), i);
    }

    warpMergeK<K>(lv, li);
    if (lane == 0) {
        #pragma unroll
        for (int j = 0; j < K; j++) {
            s_wval[wid * K + j] = lv[j];
            s_widx[wid * K + j] = li[j];
        }
    }
    __syncthreads();

    if (wid == 0) {
        float mv[K];
        int   mi[K];
        #pragma unroll
        for (int j = 0; j < K; j++) { mv[j] = -INFINITY; mi[j] = INT_MAX; }
        if (lane < WPB) {
            #pragma unroll
            for (int j = 0; j < K; j++) { mv[j] = s_wval[lane * K + j]; mi[j] = s_widx[lane * K + j]; }
        }
        warpMergeK<K>(mv, mi);
        if (lane == 0) {
            #pragma unroll
            for (int j = 0; j < K; j++) {
                out[j]     = mv[j];          // top_scores (sorted desc, ties by index)
                out[K + j] = (float)mi[j];   // top_indices (exact in fp32 for idx < 2^24)
            }
            g_done = 0;                      // reset for next graph replay
        }
    }
}

// ---------------------------------------------------------------------------
// Launch
// ---------------------------------------------------------------------------
extern "C" void kernel_launch(void* const* d_in, const int* in_sizes, int n_in,
                              void* d_out, int out_size)
{
    const float* q     = (const float*)d_in[0];   // (768,)
    const float* loc   = (const float*)d_in[1];   // (2,)
    const float* feats = (const float*)d_in[2];   // (M, 768)
    const float* locs  = (const float*)d_in[3];   // (M, 2)
    const float* meta  = (const float*)d_in[4];   // (M, 4)
    float* out = (float*)d_out;                   // [k scores | k indices]

    int M = in_sizes[2] / DIMS;
    if (M > MAXM) M = MAXM;
    int k = out_size / 2;
    if (k < 1) k = 1;
    if (k > KMAX) k = KMAX;

    const int nblk = (M + WPB - 1) / WPB;

    #define LAUNCH(KK) score_topk_fused<KK><<<nblk, TPB>>>((const float4*)q, loc, \
        (const float4*)feats, (const float2*)locs, (const float4*)meta, M, out)
    switch (k) {
        case 1: LAUNCH(1); break;
        case 2: LAUNCH(2); break;
        case 3: LAUNCH(3); break;
        case 4: LAUNCH(4); break;
        case 5: LAUNCH(5); break;
        case 6: LAUNCH(6); break;
        case 7: LAUNCH(7); break;
        default: LAUNCH(8); break;
    }
    #undef LAUNCH
}

// round 12
// speedup vs baseline: 1.0329x; 1.0037x over previous
#include <cuda_runtime.h>
#include <math.h>
#include <limits.h>

#define EPSV 1e-12f
#define DIMS 768
#define MAXM (131072)
#define KMAX 8
#define TPB 256
#define WPB (TPB / 32)
#define GRP_SHIFT 7                 // 128 blocks per group
#define GRP (1 << GRP_SHIFT)
#define MAXGRP ((MAXM / WPB + GRP - 1) / GRP)   // 128

// Scratch (no cudaMalloc allowed)
__device__ float g_scores[MAXM];
__device__ unsigned int g_done1[MAXGRP * 32];   // 128B-strided per-group counters
__device__ unsigned int g_done2 = 0;            // level-2 counter (~98 ops max)

// Ordering consistent with jax.lax.top_k: higher value first, lower index on ties.
__device__ __forceinline__ bool better(float v1, int i1, float v2, int i2) {
    return (v1 > v2) || (v1 == v2 && i1 < i2);
}

// Branchless sorted-insert into a register-resident descending top-K list.
template<int K>
__device__ __forceinline__ void insertK(float (&lv)[K], int (&li)[K], float v, int i) {
    if (!better(v, i, lv[K - 1], li[K - 1])) return;
    bool b[K];
    #pragma unroll
    for (int j = 0; j < K; j++) b[j] = better(lv[j], li[j], v, i);
    #pragma unroll
    for (int j = K - 1; j >= 1; --j) {
        lv[j] = b[j] ? lv[j] : (b[j - 1] ? v : lv[j - 1]);
        li[j] = b[j] ? li[j] : (b[j - 1] ? i : li[j - 1]);
    }
    if (!b[0]) { lv[0] = v; li[0] = i; }
}

// Full-warp merge: after this, EVERY lane holds the warp's merged top-K.
template<int K>
__device__ __forceinline__ void warpMergeK(float (&lv)[K], int (&li)[K]) {
    #pragma unroll
    for (int o = 16; o; o >>= 1) {
        float pv[K];
        int   pi[K];
        #pragma unroll
        for (int j = 0; j < K; j++) {
            pv[j] = __shfl_xor_sync(0xffffffffu, lv[j], o);
            pi[j] = __shfl_xor_sync(0xffffffffu, li[j], o);
        }
        #pragma unroll
        for (int j = 0; j < K; j++) insertK<K>(lv, li, pv[j], pi[j]);
    }
}

__device__ __forceinline__ unsigned int atom_add_release(unsigned int* p) {
    unsigned int old;
    asm volatile("atom.add.release.gpu.u32 %0, [%1], 1;"
                 : "=r"(old) : "l"(p) : "memory");
    return old;
}
__device__ __forceinline__ unsigned int atom_add_acqrel(unsigned int* p) {
    unsigned int old;
    asm volatile("atom.add.acq_rel.gpu.u32 %0, [%1], 1;"
                 : "=r"(old) : "l"(p) : "memory");
    return old;
}

// ---------------------------------------------------------------------------
// Single fused kernel: scoring (one warp per row, proven hot path) + top-k
// by the LAST block, elected through a two-level counter tree (no
// single-address atomic hotspot — that was the R10/R11 regression).
// ---------------------------------------------------------------------------
template<int K>
__global__ void __launch_bounds__(TPB)
score_topk_fused(const float4* __restrict__ q4,
                 const float*  __restrict__ loc,
                 const float4* __restrict__ feats4,
                 const float2* __restrict__ locs2,
                 const float4* __restrict__ meta4,
                 int M, float* __restrict__ out)
{
    __shared__ float s_wval[WPB * K];
    __shared__ int   s_widx[WPB * K];
    __shared__ bool  s_last;

    const int wid  = threadIdx.x >> 5;
    const int lane = threadIdx.x & 31;
    const int row  = blockIdx.x * WPB + wid;

    // ================= scoring phase (unchanged hot path) =================
    if (row < M) {
        float2 lrow = make_float2(0.f, 0.f);
        float4 mrow = make_float4(0.f, 0.f, 0.f, 0.f);
        float  l0 = 0.f, l1 = 0.f;
        if (lane == 0) {
            lrow = __ldg(locs2 + row);
            mrow = __ldg(meta4 + row);
            l0 = __ldg(loc);
            l1 = __ldg(loc + 1);
        }

        const float4* __restrict__ rp = feats4 + (size_t)row * (DIMS / 4);

        float4 a0 = __ldcs(rp + lane + 32 * 0);
        float4 a1 = __ldcs(rp + lane + 32 * 1);
        float4 a2 = __ldcs(rp + lane + 32 * 2);
        float4 a3 = __ldcs(rp + lane + 32 * 3);
        float4 a4 = __ldcs(rp + lane + 32 * 4);
        float4 a5 = __ldcs(rp + lane + 32 * 5);

        float dot = 0.f, ss = 0.f, qq = 0.f;
        {
            float4 b;
            b = __ldg(q4 + lane + 32 * 0);
            dot += a0.x*b.x + a0.y*b.y + a0.z*b.z + a0.w*b.w;
            ss  += a0.x*a0.x + a0.y*a0.y + a0.z*a0.z + a0.w*a0.w;
            qq  += b.x*b.x + b.y*b.y + b.z*b.z + b.w*b.w;
            b = __ldg(q4 + lane + 32 * 1);
            dot += a1.x*b.x + a1.y*b.y + a1.z*b.z + a1.w*b.w;
            ss  += a1.x*a1.x + a1.y*a1.y + a1.z*a1.z + a1.w*a1.w;
            qq  += b.x*b.x + b.y*b.y + b.z*b.z + b.w*b.w;
            b = __ldg(q4 + lane + 32 * 2);
            dot += a2.x*b.x + a2.y*b.y + a2.z*b.z + a2.w*b.w;
            ss  += a2.x*a2.x + a2.y*a2.y + a2.z*a2.z + a2.w*a2.w;
            qq  += b.x*b.x + b.y*b.y + b.z*b.z + b.w*b.w;
            b = __ldg(q4 + lane + 32 * 3);
            dot += a3.x*b.x + a3.y*b.y + a3.z*b.z + a3.w*b.w;
            ss  += a3.x*a3.x + a3.y*a3.y + a3.z*a3.z + a3.w*a3.w;
            qq  += b.x*b.x + b.y*b.y + b.z*b.z + b.w*b.w;
            b = __ldg(q4 + lane + 32 * 4);
            dot += a4.x*b.x + a4.y*b.y + a4.z*b.z + a4.w*b.w;
            ss  += a4.x*a4.x + a4.y*a4.y + a4.z*a4.z + a4.w*a4.w;
            qq  += b.x*b.x + b.y*b.y + b.z*b.z + b.w*b.w;
            b = __ldg(q4 + lane + 32 * 5);
            dot += a5.x*b.x + a5.y*b.y + a5.z*b.z + a5.w*b.w;
            ss  += a5.x*a5.x + a5.y*a5.y + a5.z*a5.z + a5.w*a5.w;
            qq  += b.x*b.x + b.y*b.y + b.z*b.z + b.w*b.w;
        }

        #pragma unroll
        for (int o = 16; o; o >>= 1) {
            dot += __shfl_xor_sync(0xffffffffu, dot, o);
            ss  += __shfl_xor_sync(0xffffffffu, ss,  o);
            qq  += __shfl_xor_sync(0xffffffffu, qq,  o);
        }

        if (lane == 0) {
            float qn = fmaxf(sqrtf(qq), EPSV);
            float mn = fmaxf(sqrtf(ss), EPSV);
            float sim = dot / (mn * qn);

            float dx = lrow.x - l0;
            float dy = lrow.y - l1;
            float spatial = 1.f / (1.f + sqrtf(dx * dx + dy * dy));

            // exp(-(3600 - ts)/3600) == exp(ts/3600 - 1)
            float temporal = expf(mrow.y * (1.f / 3600.f) - 1.f);

            g_scores[row] = (0.5f * sim + 0.3f * spatial + 0.2f * temporal) * mrow.x;
        }
    }

    // ============ last-block election via two-level counter tree ============
    __syncthreads();                      // all warps' score stores issued
    if (threadIdx.x == 0) {
        s_last = false;
        const int gid   = blockIdx.x >> GRP_SHIFT;
        const int gbase = gid << GRP_SHIFT;
        const int gcnt  = min(GRP, (int)gridDim.x - gbase);
        unsigned int o1 = atom_add_release(&g_done1[gid * 32]);
        if (o1 == (unsigned int)(gcnt - 1)) {        // group finisher
            g_done1[gid * 32] = 0;                   // reset (group complete: no race)
            const int ngrp = ((int)gridDim.x + GRP - 1) >> GRP_SHIFT;
            unsigned int o2 = atom_add_acqrel(&g_done2);
            if (o2 == (unsigned int)(ngrp - 1)) {    // global last
                g_done2 = 0;                         // reset for next graph replay
                s_last = true;
            }
        }
    }
    __syncthreads();
    if (!s_last) return;
    __threadfence();                      // acquire (once, one block only)

    // ================= top-k by the one surviving block =================
    float lv[K];
    int   li[K];
    #pragma unroll
    for (int j = 0; j < K; j++) { lv[j] = -INFINITY; li[j] = INT_MAX; }

    const int n4 = M >> 2;
    #pragma unroll 4
    for (int i = threadIdx.x; i < n4; i += TPB) {
        const int base = 4 * i;
        float v0 = __ldcg(&g_scores[base + 0]);   // L2 reads (coherence point)
        float v1 = __ldcg(&g_scores[base + 1]);
        float v2 = __ldcg(&g_scores[base + 2]);
        float v3 = __ldcg(&g_scores[base + 3]);
        insertK<K>(lv, li, v0, base + 0);
        insertK<K>(lv, li, v1, base + 1);
        insertK<K>(lv, li, v2, base + 2);
        insertK<K>(lv, li, v3, base + 3);
    }
    {
        int i = (n4 << 2) + threadIdx.x;  // M % 4 remainder
        if (i < M) insertK<K>(lv, li, __ldcg(&g_scores[i]), i);
    }

    warpMergeK<K>(lv, li);
    if (lane == 0) {
        #pragma unroll
        for (int j = 0; j < K; j++) {
            s_wval[wid * K + j] = lv[j];
            s_widx[wid * K + j] = li[j];
        }
    }
    __syncthreads();

    if (wid == 0) {
        float mv[K];
        int   mi[K];
        #pragma unroll
        for (int j = 0; j < K; j++) { mv[j] = -INFINITY; mi[j] = INT_MAX; }
        if (lane < WPB) {
            #pragma unroll
            for (int j = 0; j < K; j++) { mv[j] = s_wval[lane * K + j]; mi[j] = s_widx[lane * K + j]; }
        }
        warpMergeK<K>(mv, mi);
        if (lane == 0) {
            #pragma unroll
            for (int j = 0; j < K; j++) {
                out[j]     = mv[j];          // top_scores (sorted desc, ties by index)
                out[K + j] = (float)mi[j];   // top_indices (exact in fp32 for idx < 2^24)
            }
        }
    }
}

// ---------------------------------------------------------------------------
// Launch
// ---------------------------------------------------------------------------
extern "C" void kernel_launch(void* const* d_in, const int* in_sizes, int n_in,
                              void* d_out, int out_size)
{
    const float* q     = (const float*)d_in[0];   // (768,)
    const float* loc   = (const float*)d_in[1];   // (2,)
    const float* feats = (const float*)d_in[2];   // (M, 768)
    const float* locs  = (const float*)d_in[3];   // (M, 2)
    const float* meta  = (const float*)d_in[4];   // (M, 4)
    float* out = (float*)d_out;                   // [k scores | k indices]

    int M = in_sizes[2] / DIMS;
    if (M > MAXM) M = MAXM;
    int k = out_size / 2;
    if (k < 1) k = 1;
    if (k > KMAX) k = KMAX;

    const int nblk = (M + WPB - 1) / WPB;

    #define LAUNCH(KK) score_topk_fused<KK><<<nblk, TPB>>>((const float4*)q, loc, \
        (const float4*)feats, (const float2*)locs, (const float4*)meta, M, out)
    switch (k) {
        case 1: LAUNCH(1); break;
        case 2: LAUNCH(2); break;
        case 3: LAUNCH(3); break;
        case 4: LAUNCH(4); break;
        case 5: LAUNCH(5); break;
        case 6: LAUNCH(6); break;
        case 7: LAUNCH(7); break;
        default: LAUNCH(8); break;
    }
    #undef LAUNCH
}

// round 13
// speedup vs baseline: 1.1365x; 1.1003x over previous
#include <cuda_runtime.h>
#include <math.h>
#include <limits.h>

#define EPSV 1e-12f
#define DIMS 768
#define MAXM (131072)
#define KMAX 8
#define TPB 256
#define WPB (TPB / 32)
#define MINBLK 6                    // reg budget 42: keep the batched-MLP schedule
#define GRP_SHIFT 7                 // 128 blocks per group
#define GRP (1 << GRP_SHIFT)
#define MAXGRP ((MAXM / WPB + GRP - 1) / GRP)   // 128

// Scratch (no cudaMalloc allowed)
__device__ float g_scores[MAXM];
__device__ unsigned int g_done1[MAXGRP * 32];   // 128B-strided per-group counters
__device__ unsigned int g_done2 = 0;            // level-2 counter (~98 ops max)

// Ordering consistent with jax.lax.top_k: higher value first, lower index on ties.
__device__ __forceinline__ bool better(float v1, int i1, float v2, int i2) {
    return (v1 > v2) || (v1 == v2 && i1 < i2);
}

// Branchless sorted-insert into a register-resident descending top-K list.
template<int K>
__device__ __forceinline__ void insertK(float (&lv)[K], int (&li)[K], float v, int i) {
    if (!better(v, i, lv[K - 1], li[K - 1])) return;
    bool b[K];
    #pragma unroll
    for (int j = 0; j < K; j++) b[j] = better(lv[j], li[j], v, i);
    #pragma unroll
    for (int j = K - 1; j >= 1; --j) {
        lv[j] = b[j] ? lv[j] : (b[j - 1] ? v : lv[j - 1]);
        li[j] = b[j] ? li[j] : (b[j - 1] ? i : li[j - 1]);
    }
    if (!b[0]) { lv[0] = v; li[0] = i; }
}

// Full-warp merge: after this, EVERY lane holds the warp's merged top-K.
template<int K>
__device__ __forceinline__ void warpMergeK(float (&lv)[K], int (&li)[K]) {
    #pragma unroll
    for (int o = 16; o; o >>= 1) {
        float pv[K];
        int   pi[K];
        #pragma unroll
        for (int j = 0; j < K; j++) {
            pv[j] = __shfl_xor_sync(0xffffffffu, lv[j], o);
            pi[j] = __shfl_xor_sync(0xffffffffu, li[j], o);
        }
        #pragma unroll
        for (int j = 0; j < K; j++) insertK<K>(lv, li, pv[j], pi[j]);
    }
}

__device__ __forceinline__ unsigned int atom_add_release(unsigned int* p) {
    unsigned int old;
    asm volatile("atom.add.release.gpu.u32 %0, [%1], 1;"
                 : "=r"(old) : "l"(p) : "memory");
    return old;
}

// ---------------------------------------------------------------------------
// Single fused kernel: scoring (one warp per row) + top-k by the LAST block.
// __launch_bounds__(TPB, MINBLK) gives ptxas a 42-reg budget so the hot path
// keeps all 12 float4 operands live (batched MLP) — at plain launch_bounds(256)
// ptxas targeted 8 blocks/SM, capped regs at 32, serialized the loads, and the
// kernel ran 2x slow (R10-R12).
// ---------------------------------------------------------------------------
template<int K>
__global__ void __launch_bounds__(TPB, MINBLK)
score_topk_fused(const float4* __restrict__ q4,
                 const float*  __restrict__ loc,
                 const float4* __restrict__ feats4,
                 const float2* __restrict__ locs2,
                 const float4* __restrict__ meta4,
                 int M, float* __restrict__ out)
{
    __shared__ float s_wval[WPB * K];
    __shared__ int   s_widx[WPB * K];
    __shared__ bool  s_last;

    const int wid  = threadIdx.x >> 5;
    const int lane = threadIdx.x & 31;
    const int row  = blockIdx.x * WPB + wid;

    // ================= scoring phase (proven hot path) =================
    if (row < M) {
        float2 lrow = make_float2(0.f, 0.f);
        float4 mrow = make_float4(0.f, 0.f, 0.f, 0.f);
        float  l0 = 0.f, l1 = 0.f;
        if (lane == 0) {
            lrow = __ldg(locs2 + row);
            mrow = __ldg(meta4 + row);
            l0 = __ldg(loc);
            l1 = __ldg(loc + 1);
        }

        const float4* __restrict__ rp = feats4 + (size_t)row * (DIMS / 4);

        float4 a0 = __ldcs(rp + lane + 32 * 0);
        float4 a1 = __ldcs(rp + lane + 32 * 1);
        float4 a2 = __ldcs(rp + lane + 32 * 2);
        float4 a3 = __ldcs(rp + lane + 32 * 3);
        float4 a4 = __ldcs(rp + lane + 32 * 4);
        float4 a5 = __ldcs(rp + lane + 32 * 5);

        float dot = 0.f, ss = 0.f, qq = 0.f;
        {
            float4 b;
            b = __ldg(q4 + lane + 32 * 0);
            dot += a0.x*b.x + a0.y*b.y + a0.z*b.z + a0.w*b.w;
            ss  += a0.x*a0.x + a0.y*a0.y + a0.z*a0.z + a0.w*a0.w;
            qq  += b.x*b.x + b.y*b.y + b.z*b.z + b.w*b.w;
            b = __ldg(q4 + lane + 32 * 1);
            dot += a1.x*b.x + a1.y*b.y + a1.z*b.z + a1.w*b.w;
            ss  += a1.x*a1.x + a1.y*a1.y + a1.z*a1.z + a1.w*a1.w;
            qq  += b.x*b.x + b.y*b.y + b.z*b.z + b.w*b.w;
            b = __ldg(q4 + lane + 32 * 2);
            dot += a2.x*b.x + a2.y*b.y + a2.z*b.z + a2.w*b.w;
            ss  += a2.x*a2.x + a2.y*a2.y + a2.z*a2.z + a2.w*a2.w;
            qq  += b.x*b.x + b.y*b.y + b.z*b.z + b.w*b.w;
            b = __ldg(q4 + lane + 32 * 3);
            dot += a3.x*b.x + a3.y*b.y + a3.z*b.z + a3.w*b.w;
            ss  += a3.x*a3.x + a3.y*a3.y + a3.z*a3.z + a3.w*a3.w;
            qq  += b.x*b.x + b.y*b.y + b.z*b.z + b.w*b.w;
            b = __ldg(q4 + lane + 32 * 4);
            dot += a4.x*b.x + a4.y*b.y + a4.z*b.z + a4.w*b.w;
            ss  += a4.x*a4.x + a4.y*a4.y + a4.z*a4.z + a4.w*a4.w;
            qq  += b.x*b.x + b.y*b.y + b.z*b.z + b.w*b.w;
            b = __ldg(q4 + lane + 32 * 5);
            dot += a5.x*b.x + a5.y*b.y + a5.z*b.z + a5.w*b.w;
            ss  += a5.x*a5.x + a5.y*a5.y + a5.z*a5.z + a5.w*a5.w;
            qq  += b.x*b.x + b.y*b.y + b.z*b.z + b.w*b.w;
        }

        #pragma unroll
        for (int o = 16; o; o >>= 1) {
            dot += __shfl_xor_sync(0xffffffffu, dot, o);
            ss  += __shfl_xor_sync(0xffffffffu, ss,  o);
            qq  += __shfl_xor_sync(0xffffffffu, qq,  o);
        }

        if (lane == 0) {
            float qn = fmaxf(sqrtf(qq), EPSV);
            float mn = fmaxf(sqrtf(ss), EPSV);
            float sim = dot / (mn * qn);

            float dx = lrow.x - l0;
            float dy = lrow.y - l1;
            float spatial = 1.f / (1.f + sqrtf(dx * dx + dy * dy));

            // exp(-(3600 - ts)/3600) == exp(ts/3600 - 1)
            float temporal = expf(mrow.y * (1.f / 3600.f) - 1.f);

            g_scores[row] = (0.5f * sim + 0.3f * spatial + 0.2f * temporal) * mrow.x;
        }
    }

    // ============ last-block election via two-level counter tree ============
    __syncthreads();                      // all warps' score stores issued
    if (threadIdx.x == 0) {
        s_last = false;
        const int gid   = blockIdx.x >> GRP_SHIFT;
        const int gbase = gid << GRP_SHIFT;
        const int gcnt  = min(GRP, (int)gridDim.x - gbase);
        unsigned int o1 = atom_add_release(&g_done1[gid * 32]);
        if (o1 == (unsigned int)(gcnt - 1)) {        // group finisher (~98 blocks)
            __threadfence();                          // acquire group members' releases
            g_done1[gid * 32] = 0;                   // reset (group complete: no race)
            const int ngrp = ((int)gridDim.x + GRP - 1) >> GRP_SHIFT;
            unsigned int o2 = atom_add_release(&g_done2);
            if (o2 == (unsigned int)(ngrp - 1)) {    // global last
                g_done2 = 0;                         // reset for next graph replay
                s_last = true;
            }
        }
    }
    __syncthreads();
    if (!s_last) return;
    __threadfence();                      // acquire (once, one block only)

    // ================= top-k by the one surviving block =================
    float lv[K];
    int   li[K];
    #pragma unroll
    for (int j = 0; j < K; j++) { lv[j] = -INFINITY; li[j] = INT_MAX; }

    const int n4 = M >> 2;
    #pragma unroll 4
    for (int i = threadIdx.x; i < n4; i += TPB) {
        const int base = 4 * i;
        float v0 = __ldcg(&g_scores[base + 0]);   // L2 reads (coherence point)
        float v1 = __ldcg(&g_scores[base + 1]);
        float v2 = __ldcg(&g_scores[base + 2]);
        float v3 = __ldcg(&g_scores[base + 3]);
        insertK<K>(lv, li, v0, base + 0);
        insertK<K>(lv, li, v1, base + 1);
        insertK<K>(lv, li, v2, base + 2);
        insertK<K>(lv, li, v3, base + 3);
    }
    {
        int i = (n4 << 2) + threadIdx.x;  // M % 4 remainder
        if (i < M) insertK<K>(lv, li, __ldcg(&g_scores[i]), i);
    }

    warpMergeK<K>(lv, li);
    if (lane == 0) {
        #pragma unroll
        for (int j = 0; j < K; j++) {
            s_wval[wid * K + j] = lv[j];
            s_widx[wid * K + j] = li[j];
        }
    }
    __syncthreads();

    if (wid == 0) {
        float mv[K];
        int   mi[K];
        #pragma unroll
        for (int j = 0; j < K; j++) { mv[j] = -INFINITY; mi[j] = INT_MAX; }
        if (lane < WPB) {
            #pragma unroll
            for (int j = 0; j < K; j++) { mv[j] = s_wval[lane * K + j]; mi[j] = s_widx[lane * K + j]; }
        }
        warpMergeK<K>(mv, mi);
        if (lane == 0) {
            #pragma unroll
            for (int j = 0; j < K; j++) {
                out[j]     = mv[j];          // top_scores (sorted desc, ties by index)
                out[K + j] = (float)mi[j];   // top_indices (exact in fp32 for idx < 2^24)
            }
        }
    }
}

// ---------------------------------------------------------------------------
// Launch
// ---------------------------------------------------------------------------
extern "C" void kernel_launch(void* const* d_in, const int* in_sizes, int n_in,
                              void* d_out, int out_size)
{
    const float* q     = (const float*)d_in[0];   // (768,)
    const float* loc   = (const float*)d_in[1];   // (2,)
    const float* feats = (const float*)d_in[2];   // (M, 768)
    const float* locs  = (const float*)d_in[3];   // (M, 2)
    const float* meta  = (const float*)d_in[4];   // (M, 4)
    float* out = (float*)d_out;                   // [k scores | k indices]

    int M = in_sizes[2] / DIMS;
    if (M > MAXM) M = MAXM;
    int k = out_size / 2;
    if (k < 1) k = 1;
    if (k > KMAX) k = KMAX;

    const int nblk = (M + WPB - 1) / WPB;

    #define LAUNCH(KK) score_topk_fused<KK><<<nblk, TPB>>>((const float4*)q, loc, \
        (const float4*)feats, (const float2*)locs, (const float4*)meta, M, out)
    switch (k) {
        case 1: LAUNCH(1); break;
        case 2: LAUNCH(2); break;
        case 3: LAUNCH(3); break;
        case 4: LAUNCH(4); break;
        case 5: LAUNCH(5); break;
        case 6: LAUNCH(6); break;
        case 7: LAUNCH(7); break;
        default: LAUNCH(8); break;
    }
    #undef LAUNCH
}

// round 14
// speedup vs baseline: 1.7443x; 1.5348x over previous
#include <cuda_runtime.h>
#include <math.h>
#include <limits.h>

#define EPSV 1e-12f
#define DIMS 768
#define MAXM (131072)
#define KMAX 8
#define NBLK_T 148               // tail blocks: 148*256 threads >= MAXM/4 float4s
#define TPB 256
#define WPB (TPB / 32)

// Scratch (no cudaMalloc allowed)
__device__ __align__(16) float g_scores[MAXM];
__device__ float g_cand_val[NBLK_T * KMAX];
__device__ int   g_cand_idx[NBLK_T * KMAX];
__device__ unsigned int g_done = 0;   // last-block counter (reset each run)

// Ordering consistent with jax.lax.top_k: higher value first, lower index on ties.
__device__ __forceinline__ bool better(float v1, int i1, float v2, int i2) {
    return (v1 > v2) || (v1 == v2 && i1 < i2);
}

// Branchless sorted-insert into a register-resident descending top-K list.
// All indices compile-time -> stays in registers (no LDL/STL).
template<int K>
__device__ __forceinline__ void insertK(float (&lv)[K], int (&li)[K], float v, int i) {
    if (!better(v, i, lv[K - 1], li[K - 1])) return;
    bool b[K];
    #pragma unroll
    for (int j = 0; j < K; j++) b[j] = better(lv[j], li[j], v, i);
    #pragma unroll
    for (int j = K - 1; j >= 1; --j) {
        lv[j] = b[j] ? lv[j] : (b[j - 1] ? v : lv[j - 1]);
        li[j] = b[j] ? li[j] : (b[j - 1] ? i : li[j - 1]);
    }
    if (!b[0]) { lv[0] = v; li[0] = i; }
}

// Full-warp merge: after this, EVERY lane holds the warp's merged top-K.
template<int K>
__device__ __forceinline__ void warpMergeK(float (&lv)[K], int (&li)[K]) {
    #pragma unroll
    for (int o = 16; o; o >>= 1) {
        float pv[K];
        int   pi[K];
        #pragma unroll
        for (int j = 0; j < K; j++) {
            pv[j] = __shfl_xor_sync(0xffffffffu, lv[j], o);
            pi[j] = __shfl_xor_sync(0xffffffffu, li[j], o);
        }
        #pragma unroll
        for (int j = 0; j < K; j++) insertK<K>(lv, li, pv[j], pi[j]);
    }
}

// Block merge: warp lists -> shared -> warp 0 merges; afterwards warp 0's
// lanes all hold the block's top-K. Returns in (lv, li) for warp 0 only.
template<int K>
__device__ __forceinline__ void blockMergeK(float (&lv)[K], int (&li)[K],
                                            float* s_wval, int* s_widx,
                                            int wid, int lane) {
    warpMergeK<K>(lv, li);
    if (lane == 0) {
        #pragma unroll
        for (int j = 0; j < K; j++) {
            s_wval[wid * K + j] = lv[j];
            s_widx[wid * K + j] = li[j];
        }
    }
    __syncthreads();
    if (wid == 0) {
        #pragma unroll
        for (int j = 0; j < K; j++) { lv[j] = -INFINITY; li[j] = INT_MAX; }
        if (lane < WPB) {
            #pragma unroll
            for (int j = 0; j < K; j++) { lv[j] = s_wval[lane * K + j]; li[j] = s_widx[lane * K + j]; }
        }
        warpMergeK<K>(lv, li);
    }
}

// ---------------------------------------------------------------------------
// Kernel 1: fused scoring, one warp per memory row. Barrier-free (proven R5).
// ---------------------------------------------------------------------------
__global__ void __launch_bounds__(TPB)
score_kernel(const float4* __restrict__ q4,
             const float*  __restrict__ loc,
             const float4* __restrict__ feats4,
             const float2* __restrict__ locs2,
             const float4* __restrict__ meta4,
             int M)
{
    const int wid  = threadIdx.x >> 5;
    const int lane = threadIdx.x & 31;
    const int row  = blockIdx.x * WPB + wid;
    if (row >= M) return;

    float2 lrow = make_float2(0.f, 0.f);
    float4 mrow = make_float4(0.f, 0.f, 0.f, 0.f);
    float  l0 = 0.f, l1 = 0.f;
    if (lane == 0) {
        lrow = __ldg(locs2 + row);
        mrow = __ldg(meta4 + row);
        l0 = __ldg(loc);
        l1 = __ldg(loc + 1);
    }

    const float4* __restrict__ rp = feats4 + (size_t)row * (DIMS / 4);

    float4 a0 = __ldcs(rp + lane + 32 * 0);
    float4 a1 = __ldcs(rp + lane + 32 * 1);
    float4 a2 = __ldcs(rp + lane + 32 * 2);
    float4 a3 = __ldcs(rp + lane + 32 * 3);
    float4 a4 = __ldcs(rp + lane + 32 * 4);
    float4 a5 = __ldcs(rp + lane + 32 * 5);

    float dot = 0.f, ss = 0.f, qq = 0.f;
    {
        float4 b;
        b = __ldg(q4 + lane + 32 * 0);
        dot += a0.x*b.x + a0.y*b.y + a0.z*b.z + a0.w*b.w;
        ss  += a0.x*a0.x + a0.y*a0.y + a0.z*a0.z + a0.w*a0.w;
        qq  += b.x*b.x + b.y*b.y + b.z*b.z + b.w*b.w;
        b = __ldg(q4 + lane + 32 * 1);
        dot += a1.x*b.x + a1.y*b.y + a1.z*b.z + a1.w*b.w;
        ss  += a1.x*a1.x + a1.y*a1.y + a1.z*a1.z + a1.w*a1.w;
        qq  += b.x*b.x + b.y*b.y + b.z*b.z + b.w*b.w;
        b = __ldg(q4 + lane + 32 * 2);
        dot += a2.x*b.x + a2.y*b.y + a2.z*b.z + a2.w*b.w;
        ss  += a2.x*a2.x + a2.y*a2.y + a2.z*a2.z + a2.w*a2.w;
        qq  += b.x*b.x + b.y*b.y + b.z*b.z + b.w*b.w;
        b = __ldg(q4 + lane + 32 * 3);
        dot += a3.x*b.x + a3.y*b.y + a3.z*b.z + a3.w*b.w;
        ss  += a3.x*a3.x + a3.y*a3.y + a3.z*a3.z + a3.w*a3.w;
        qq  += b.x*b.x + b.y*b.y + b.z*b.z + b.w*b.w;
        b = __ldg(q4 + lane + 32 * 4);
        dot += a4.x*b.x + a4.y*b.y + a4.z*b.z + a4.w*b.w;
        ss  += a4.x*a4.x + a4.y*a4.y + a4.z*a4.z + a4.w*a4.w;
        qq  += b.x*b.x + b.y*b.y + b.z*b.z + b.w*b.w;
        b = __ldg(q4 + lane + 32 * 5);
        dot += a5.x*b.x + a5.y*b.y + a5.z*b.z + a5.w*b.w;
        ss  += a5.x*a5.x + a5.y*a5.y + a5.z*a5.z + a5.w*a5.w;
        qq  += b.x*b.x + b.y*b.y + b.z*b.z + b.w*b.w;
    }

    #pragma unroll
    for (int o = 16; o; o >>= 1) {
        dot += __shfl_xor_sync(0xffffffffu, dot, o);
        ss  += __shfl_xor_sync(0xffffffffu, ss,  o);
        qq  += __shfl_xor_sync(0xffffffffu, qq,  o);
    }

    if (lane == 0) {
        float qn = fmaxf(sqrtf(qq), EPSV);
        float mn = fmaxf(sqrtf(ss), EPSV);
        float sim = dot / (mn * qn);

        float dx = lrow.x - l0;
        float dy = lrow.y - l1;
        float spatial = 1.f / (1.f + sqrtf(dx * dx + dy * dy));

        // exp(-(3600 - ts)/3600) == exp(ts/3600 - 1)
        float temporal = expf(mrow.y * (1.f / 3600.f) - 1.f);

        g_scores[row] = (0.5f * sim + 0.3f * spatial + 0.2f * temporal) * mrow.x;
    }
}

// ---------------------------------------------------------------------------
// Kernel 2: loop-free top-k. EXACTLY ONE float4 per thread (no latency-serial
// grid-stride loop — that was R8/R9's 12-16us), then register merges; the
// LAST block merges the 148*K candidates and writes the output.
// ---------------------------------------------------------------------------
template<int K>
__global__ void __launch_bounds__(TPB)
topk_tail(int M, float* __restrict__ out)
{
    __shared__ float s_wval[WPB * K];
    __shared__ int   s_widx[WPB * K];
    __shared__ bool  s_last;

    const int wid  = threadIdx.x >> 5;
    const int lane = threadIdx.x & 31;
    const int gid  = blockIdx.x * TPB + threadIdx.x;

    float lv[K];
    int   li[K];
    #pragma unroll
    for (int j = 0; j < K; j++) { lv[j] = -INFINITY; li[j] = INT_MAX; }

    // ---- phase 1: one float4 per thread (single parallel L2 round-trip) ----
    const int n4 = M >> 2;
    if (gid < n4) {
        float4 v = *((const float4*)g_scores + gid);
        const int base = 4 * gid;
        insertK<K>(lv, li, v.x, base + 0);
        insertK<K>(lv, li, v.y, base + 1);
        insertK<K>(lv, li, v.z, base + 2);
        insertK<K>(lv, li, v.w, base + 3);
    } else {
        const int r = (n4 << 2) + (gid - n4);   // M % 4 remainder elements
        if (r < M) insertK<K>(lv, li, g_scores[r], r);
    }

    // ---- phase 2: warp + block register merges, publish block candidates ----
    blockMergeK<K>(lv, li, s_wval, s_widx, wid, lane);
    if (wid == 0 && lane == 0) {
        #pragma unroll
        for (int j = 0; j < K; j++) {
            g_cand_val[blockIdx.x * K + j] = lv[j];
            g_cand_idx[blockIdx.x * K + j] = li[j];
        }
        __threadfence();                       // publish candidates
        unsigned int t = atomicAdd(&g_done, 1u);
        s_last = (t == (unsigned int)(gridDim.x - 1));
    }
    __syncthreads();
    if (!s_last) return;
    __threadfence();                           // acquire all candidates

    // ---- phase 3: last block merges 148*K candidates (<=3 per thread) ----
    #pragma unroll
    for (int j = 0; j < K; j++) { lv[j] = -INFINITY; li[j] = INT_MAX; }
    const int ncand = (int)gridDim.x * K;
    for (int p = threadIdx.x; p < ncand; p += TPB)
        insertK<K>(lv, li, __ldcg(&g_cand_val[p]), __ldcg(&g_cand_idx[p]));

    __syncthreads();                           // reuse of s_wval/s_widx below
    blockMergeK<K>(lv, li, s_wval, s_widx, wid, lane);
    if (wid == 0 && lane == 0) {
        #pragma unroll
        for (int j = 0; j < K; j++) {
            out[j]     = lv[j];          // top_scores (sorted desc, ties by index)
            out[K + j] = (float)li[j];   // top_indices (exact in fp32 for idx < 2^24)
        }
        g_done = 0;                      // reset for next graph replay
    }
}

// ---------------------------------------------------------------------------
// Launch
// ---------------------------------------------------------------------------
extern "C" void kernel_launch(void* const* d_in, const int* in_sizes, int n_in,
                              void* d_out, int out_size)
{
    const float* q     = (const float*)d_in[0];   // (768,)
    const float* loc   = (const float*)d_in[1];   // (2,)
    const float* feats = (const float*)d_in[2];   // (M, 768)
    const float* locs  = (const float*)d_in[3];   // (M, 2)
    const float* meta  = (const float*)d_in[4];   // (M, 4)
    float* out = (float*)d_out;                   // [k scores | k indices]

    int M = in_sizes[2] / DIMS;
    if (M > MAXM) M = MAXM;
    int k = out_size / 2;
    if (k < 1) k = 1;
    if (k > KMAX) k = KMAX;

    const int nblk_score = (M + WPB - 1) / WPB;

    score_kernel<<<nblk_score, TPB>>>((const float4*)q, loc,
                                      (const float4*)feats,
                                      (const float2*)locs,
                                      (const float4*)meta, M);

    switch (k) {
        case 1: topk_tail<1><<<NBLK_T, TPB>>>(M, out); break;
        case 2: topk_tail<2><<<NBLK_T, TPB>>>(M, out); break;
        case 3: topk_tail<3><<<NBLK_T, TPB>>>(M, out); break;
        case 4: topk_tail<4><<<NBLK_T, TPB>>>(M, out); break;
        case 5: topk_tail<5><<<NBLK_T, TPB>>>(M, out); break;
        case 6: topk_tail<6><<<NBLK_T, TPB>>>(M, out); break;
        case 7: topk_tail<7><<<NBLK_T, TPB>>>(M, out); break;
        default: topk_tail<8><<<NBLK_T, TPB>>>(M, out); break;
    }
}

// round 15
// speedup vs baseline: 1.8122x; 1.0390x over previous
#include <cuda_runtime.h>
#include <math.h>
#include <limits.h>

#define EPSV 1e-12f
#define DIMS 768
#define MAXM (131072)
#define KMAX 8
#define NBLK_T 148               // tail blocks: 148*256 threads >= MAXM/4 float4s
#define TPB 256
#define WPB (TPB / 32)

// Scratch (no cudaMalloc allowed)
__device__ __align__(16) float g_scores[MAXM];
__device__ float g_cand_val[NBLK_T * KMAX];
__device__ int   g_cand_idx[NBLK_T * KMAX];
__device__ unsigned int g_done = 0;   // last-block counter (reset each run)

// Ordering consistent with jax.lax.top_k: higher value first, lower index on ties.
__device__ __forceinline__ bool better(float v1, int i1, float v2, int i2) {
    return (v1 > v2) || (v1 == v2 && i1 < i2);
}

// Branchless sorted-insert into a register-resident descending top-K list.
template<int K>
__device__ __forceinline__ void insertK(float (&lv)[K], int (&li)[K], float v, int i) {
    if (!better(v, i, lv[K - 1], li[K - 1])) return;
    bool b[K];
    #pragma unroll
    for (int j = 0; j < K; j++) b[j] = better(lv[j], li[j], v, i);
    #pragma unroll
    for (int j = K - 1; j >= 1; --j) {
        lv[j] = b[j] ? lv[j] : (b[j - 1] ? v : lv[j - 1]);
        li[j] = b[j] ? li[j] : (b[j - 1] ? i : li[j - 1]);
    }
    if (!b[0]) { lv[0] = v; li[0] = i; }
}

// Full-warp merge: after this, EVERY lane holds the warp's merged top-K.
template<int K>
__device__ __forceinline__ void warpMergeK(float (&lv)[K], int (&li)[K]) {
    #pragma unroll
    for (int o = 16; o; o >>= 1) {
        float pv[K];
        int   pi[K];
        #pragma unroll
        for (int j = 0; j < K; j++) {
            pv[j] = __shfl_xor_sync(0xffffffffu, lv[j], o);
            pi[j] = __shfl_xor_sync(0xffffffffu, li[j], o);
        }
        #pragma unroll
        for (int j = 0; j < K; j++) insertK<K>(lv, li, pv[j], pi[j]);
    }
}

// Block merge: warp lists -> shared -> warp 0 merges (result in warp 0's regs).
template<int K>
__device__ __forceinline__ void blockMergeK(float (&lv)[K], int (&li)[K],
                                            float* s_wval, int* s_widx,
                                            int wid, int lane) {
    warpMergeK<K>(lv, li);
    if (lane == 0) {
        #pragma unroll
        for (int j = 0; j < K; j++) {
            s_wval[wid * K + j] = lv[j];
            s_widx[wid * K + j] = li[j];
        }
    }
    __syncthreads();
    if (wid == 0) {
        #pragma unroll
        for (int j = 0; j < K; j++) { lv[j] = -INFINITY; li[j] = INT_MAX; }
        if (lane < WPB) {
            #pragma unroll
            for (int j = 0; j < K; j++) { lv[j] = s_wval[lane * K + j]; li[j] = s_widx[lane * K + j]; }
        }
        warpMergeK<K>(lv, li);
    }
}

// ---------------------------------------------------------------------------
// Kernel 1: fused scoring, TWO rows per warp. 12 batched float4 loads per
// warp (better duty cycle than 6), q-chunk shared by both rows, qq computed
// once per warp-pair, epilogues on lanes 0 and 1 in parallel. Barrier-free.
// ---------------------------------------------------------------------------
__global__ void __launch_bounds__(TPB, 3)
score_kernel(const float4* __restrict__ q4,
             const float*  __restrict__ loc,
             const float4* __restrict__ feats4,
             const float2* __restrict__ locs2,
             const float4* __restrict__ meta4,
             int M)
{
    const int wid  = threadIdx.x >> 5;
    const int lane = threadIdx.x & 31;
    const int pair = blockIdx.x * WPB + wid;
    const int row0 = pair * 2;
    const int row1 = row0 + 1;
    if (row0 >= M) return;
    const bool has1 = (row1 < M);

    // Epilogue loads early (latency hidden under the feats stream).
    // lane 0 -> row0's locs/meta, lane 1 -> row1's.
    float2 lrow = make_float2(0.f, 0.f);
    float4 mrow = make_float4(0.f, 0.f, 0.f, 0.f);
    float  l0 = 0.f, l1 = 0.f;
    if (lane < 2) {
        int r = lane == 0 ? row0 : (has1 ? row1 : row0);
        lrow = __ldg(locs2 + r);
        mrow = __ldg(meta4 + r);
        l0 = __ldg(loc);
        l1 = __ldg(loc + 1);
    }

    const float4* __restrict__ rp0 = feats4 + (size_t)row0 * (DIMS / 4);
    const float4* __restrict__ rp1 = has1 ? (rp0 + (DIMS / 4)) : rp0;

    // Batch all 12 row loads up-front (MLP=12/warp), streaming (read-once).
    float4 a0 = __ldcs(rp0 + lane + 32 * 0);
    float4 a1 = __ldcs(rp0 + lane + 32 * 1);
    float4 a2 = __ldcs(rp0 + lane + 32 * 2);
    float4 a3 = __ldcs(rp0 + lane + 32 * 3);
    float4 a4 = __ldcs(rp0 + lane + 32 * 4);
    float4 a5 = __ldcs(rp0 + lane + 32 * 5);
    float4 c0 = __ldcs(rp1 + lane + 32 * 0);
    float4 c1 = __ldcs(rp1 + lane + 32 * 1);
    float4 c2 = __ldcs(rp1 + lane + 32 * 2);
    float4 c3 = __ldcs(rp1 + lane + 32 * 3);
    float4 c4 = __ldcs(rp1 + lane + 32 * 4);
    float4 c5 = __ldcs(rp1 + lane + 32 * 5);

    float dot0 = 0.f, ss0 = 0.f, dot1 = 0.f, ss1 = 0.f, qq = 0.f;
    {
        float4 b;
        b = __ldg(q4 + lane + 32 * 0);
        qq   += b.x*b.x + b.y*b.y + b.z*b.z + b.w*b.w;
        dot0 += a0.x*b.x + a0.y*b.y + a0.z*b.z + a0.w*b.w;
        ss0  += a0.x*a0.x + a0.y*a0.y + a0.z*a0.z + a0.w*a0.w;
        dot1 += c0.x*b.x + c0.y*b.y + c0.z*b.z + c0.w*b.w;
        ss1  += c0.x*c0.x + c0.y*c0.y + c0.z*c0.z + c0.w*c0.w;
        b = __ldg(q4 + lane + 32 * 1);
        qq   += b.x*b.x + b.y*b.y + b.z*b.z + b.w*b.w;
        dot0 += a1.x*b.x + a1.y*b.y + a1.z*b.z + a1.w*b.w;
        ss0  += a1.x*a1.x + a1.y*a1.y + a1.z*a1.z + a1.w*a1.w;
        dot1 += c1.x*b.x + c1.y*b.y + c1.z*b.z + c1.w*b.w;
        ss1  += c1.x*c1.x + c1.y*c1.y + c1.z*c1.z + c1.w*c1.w;
        b = __ldg(q4 + lane + 32 * 2);
        qq   += b.x*b.x + b.y*b.y + b.z*b.z + b.w*b.w;
        dot0 += a2.x*b.x + a2.y*b.y + a2.z*b.z + a2.w*b.w;
        ss0  += a2.x*a2.x + a2.y*a2.y + a2.z*a2.z + a2.w*a2.w;
        dot1 += c2.x*b.x + c2.y*b.y + c2.z*b.z + c2.w*b.w;
        ss1  += c2.x*c2.x + c2.y*c2.y + c2.z*c2.z + c2.w*c2.w;
        b = __ldg(q4 + lane + 32 * 3);
        qq   += b.x*b.x + b.y*b.y + b.z*b.z + b.w*b.w;
        dot0 += a3.x*b.x + a3.y*b.y + a3.z*b.z + a3.w*b.w;
        ss0  += a3.x*a3.x + a3.y*a3.y + a3.z*a3.z + a3.w*a3.w;
        dot1 += c3.x*b.x + c3.y*b.y + c3.z*b.z + c3.w*b.w;
        ss1  += c3.x*c3.x + c3.y*c3.y + c3.z*c3.z + c3.w*c3.w;
        b = __ldg(q4 + lane + 32 * 4);
        qq   += b.x*b.x + b.y*b.y + b.z*b.z + b.w*b.w;
        dot0 += a4.x*b.x + a4.y*b.y + a4.z*b.z + a4.w*b.w;
        ss0  += a4.x*a4.x + a4.y*a4.y + a4.z*a4.z + a4.w*a4.w;
        dot1 += c4.x*b.x + c4.y*b.y + c4.z*b.z + c4.w*b.w;
        ss1  += c4.x*c4.x + c4.y*c4.y + c4.z*c4.z + c4.w*c4.w;
        b = __ldg(q4 + lane + 32 * 5);
        qq   += b.x*b.x + b.y*b.y + b.z*b.z + b.w*b.w;
        dot0 += a5.x*b.x + a5.y*b.y + a5.z*b.z + a5.w*b.w;
        ss0  += a5.x*a5.x + a5.y*a5.y + a5.z*a5.z + a5.w*a5.w;
        dot1 += c5.x*b.x + c5.y*b.y + c5.z*b.z + c5.w*b.w;
        ss1  += c5.x*c5.x + c5.y*c5.y + c5.z*c5.z + c5.w*c5.w;
    }

    #pragma unroll
    for (int o = 16; o; o >>= 1) {
        dot0 += __shfl_xor_sync(0xffffffffu, dot0, o);
        ss0  += __shfl_xor_sync(0xffffffffu, ss0,  o);
        dot1 += __shfl_xor_sync(0xffffffffu, dot1, o);
        ss1  += __shfl_xor_sync(0xffffffffu, ss1,  o);
        qq   += __shfl_xor_sync(0xffffffffu, qq,   o);
    }

    // Parallel epilogues: lane 0 finishes row0, lane 1 finishes row1.
    if (lane == 0 || (lane == 1 && has1)) {
        const float dot = (lane == 0) ? dot0 : dot1;
        const float ss  = (lane == 0) ? ss0  : ss1;
        const int   r   = (lane == 0) ? row0 : row1;

        float qn = fmaxf(sqrtf(qq), EPSV);
        float mn = fmaxf(sqrtf(ss), EPSV);
        float sim = dot / (mn * qn);

        float dx = lrow.x - l0;
        float dy = lrow.y - l1;
        float spatial = 1.f / (1.f + sqrtf(dx * dx + dy * dy));

        // exp(-(3600 - ts)/3600) == exp(ts/3600 - 1)
        float temporal = expf(mrow.y * (1.f / 3600.f) - 1.f);

        g_scores[r] = (0.5f * sim + 0.3f * spatial + 0.2f * temporal) * mrow.x;
    }
}

// ---------------------------------------------------------------------------
// Kernel 2: loop-free top-k (R14, at the second-kernel fixed-cost floor).
// ---------------------------------------------------------------------------
template<int K>
__global__ void __launch_bounds__(TPB)
topk_tail(int M, float* __restrict__ out)
{
    __shared__ float s_wval[WPB * K];
    __shared__ int   s_widx[WPB * K];
    __shared__ bool  s_last;

    const int wid  = threadIdx.x >> 5;
    const int lane = threadIdx.x & 31;
    const int gid  = blockIdx.x * TPB + threadIdx.x;

    float lv[K];
    int   li[K];
    #pragma unroll
    for (int j = 0; j < K; j++) { lv[j] = -INFINITY; li[j] = INT_MAX; }

    // ---- phase 1: one float4 per thread (single parallel L2 round-trip) ----
    const int n4 = M >> 2;
    if (gid < n4) {
        float4 v = *((const float4*)g_scores + gid);
        const int base = 4 * gid;
        insertK<K>(lv, li, v.x, base + 0);
        insertK<K>(lv, li, v.y, base + 1);
        insertK<K>(lv, li, v.z, base + 2);
        insertK<K>(lv, li, v.w, base + 3);
    } else {
        const int r = (n4 << 2) + (gid - n4);   // M % 4 remainder elements
        if (r < M) insertK<K>(lv, li, g_scores[r], r);
    }

    // ---- phase 2: warp + block register merges, publish block candidates ----
    blockMergeK<K>(lv, li, s_wval, s_widx, wid, lane);
    if (wid == 0 && lane == 0) {
        #pragma unroll
        for (int j = 0; j < K; j++) {
            g_cand_val[blockIdx.x * K + j] = lv[j];
            g_cand_idx[blockIdx.x * K + j] = li[j];
        }
        __threadfence();                       // publish candidates
        unsigned int t = atomicAdd(&g_done, 1u);
        s_last = (t == (unsigned int)(gridDim.x - 1));
    }
    __syncthreads();
    if (!s_last) return;
    __threadfence();                           // acquire all candidates

    // ---- phase 3: last block merges 148*K candidates (<=3 per thread) ----
    #pragma unroll
    for (int j = 0; j < K; j++) { lv[j] = -INFINITY; li[j] = INT_MAX; }
    const int ncand = (int)gridDim.x * K;
    for (int p = threadIdx.x; p < ncand; p += TPB)
        insertK<K>(lv, li, __ldcg(&g_cand_val[p]), __ldcg(&g_cand_idx[p]));

    __syncthreads();                           // reuse of s_wval/s_widx below
    blockMergeK<K>(lv, li, s_wval, s_widx, wid, lane);
    if (wid == 0 && lane == 0) {
        #pragma unroll
        for (int j = 0; j < K; j++) {
            out[j]     = lv[j];          // top_scores (sorted desc, ties by index)
            out[K + j] = (float)li[j];   // top_indices (exact in fp32 for idx < 2^24)
        }
        g_done = 0;                      // reset for next graph replay
    }
}

// ---------------------------------------------------------------------------
// Launch
// ---------------------------------------------------------------------------
extern "C" void kernel_launch(void* const* d_in, const int* in_sizes, int n_in,
                              void* d_out, int out_size)
{
    const float* q     = (const float*)d_in[0];   // (768,)
    const float* loc   = (const float*)d_in[1];   // (2,)
    const float* feats = (const float*)d_in[2];   // (M, 768)
    const float* locs  = (const float*)d_in[3];   // (M, 2)
    const float* meta  = (const float*)d_in[4];   // (M, 4)
    float* out = (float*)d_out;                   // [k scores | k indices]

    int M = in_sizes[2] / DIMS;
    if (M > MAXM) M = MAXM;
    int k = out_size / 2;
    if (k < 1) k = 1;
    if (k > KMAX) k = KMAX;

    const int npairs = (M + 1) / 2;
    const int nblk_score = (npairs + WPB - 1) / WPB;

    score_kernel<<<nblk_score, TPB>>>((const float4*)q, loc,
                                      (const float4*)feats,
                                      (const float2*)locs,
                                      (const float4*)meta, M);

    switch (k) {
        case 1: topk_tail<1><<<NBLK_T, TPB>>>(M, out); break;
        case 2: topk_tail<2><<<NBLK_T, TPB>>>(M, out); break;
        case 3: topk_tail<3><<<NBLK_T, TPB>>>(M, out); break;
        case 4: topk_tail<4><<<NBLK_T, TPB>>>(M, out); break;
        case 5: topk_tail<5><<<NBLK_T, TPB>>>(M, out); break;
        case 6: topk_tail<6><<<NBLK_T, TPB>>>(M, out); break;
        case 7: topk_tail<7><<<NBLK_T, TPB>>>(M, out); break;
        default: topk_tail<8><<<NBLK_T, TPB>>>(M, out); break;
    }
}

// round 16
// speedup vs baseline: 1.9817x; 1.0935x over previous
#include <cuda_runtime.h>
#include <math.h>
#include <limits.h>

#define EPSV 1e-12f
#define DIMS 768
#define MAXM (131072)
#define KMAX 8
#define NBLK_T 148               // tail blocks: 148*256 threads >= MAXM/4 float4s
#define TPB 256
#define WPB (TPB / 32)
#define RPW 3                    // rows per warp in the score kernel

// Scratch (no cudaMalloc allowed)
__device__ __align__(16) float g_scores[MAXM];
__device__ float g_cand_val[NBLK_T * KMAX];
__device__ int   g_cand_idx[NBLK_T * KMAX];
__device__ unsigned int g_done = 0;   // last-block counter (reset each run)

// Ordering consistent with jax.lax.top_k: higher value first, lower index on ties.
__device__ __forceinline__ bool better(float v1, int i1, float v2, int i2) {
    return (v1 > v2) || (v1 == v2 && i1 < i2);
}

// Branchless sorted-insert into a register-resident descending top-K list.
template<int K>
__device__ __forceinline__ void insertK(float (&lv)[K], int (&li)[K], float v, int i) {
    if (!better(v, i, lv[K - 1], li[K - 1])) return;
    bool b[K];
    #pragma unroll
    for (int j = 0; j < K; j++) b[j] = better(lv[j], li[j], v, i);
    #pragma unroll
    for (int j = K - 1; j >= 1; --j) {
        lv[j] = b[j] ? lv[j] : (b[j - 1] ? v : lv[j - 1]);
        li[j] = b[j] ? li[j] : (b[j - 1] ? i : li[j - 1]);
    }
    if (!b[0]) { lv[0] = v; li[0] = i; }
}

// ---------------------------------------------------------------------------
// Kernel 1: fused scoring, THREE rows per warp. 18 batched float4 loads per
// warp, q-chunk shared by all rows, qq reduced once per warp, epilogues on
// lanes 0-2 in parallel. Barrier-free. launch_bounds(256,2): 128-reg budget
// keeps all 18 row operands live (batched MLP).
// ---------------------------------------------------------------------------
__global__ void __launch_bounds__(TPB, 2)
score_kernel(const float4* __restrict__ q4,
             const float*  __restrict__ loc,
             const float4* __restrict__ feats4,
             const float2* __restrict__ locs2,
             const float4* __restrict__ meta4,
             int M)
{
    const int wid  = threadIdx.x >> 5;
    const int lane = threadIdx.x & 31;
    const int w    = blockIdx.x * WPB + wid;
    const int row0 = w * RPW;
    if (row0 >= M) return;
    const bool has1 = (row0 + 1 < M);
    const bool has2 = (row0 + 2 < M);

    // Epilogue loads early; lane i (i<3) handles row0+i.
    float2 lrow = make_float2(0.f, 0.f);
    float4 mrow = make_float4(0.f, 0.f, 0.f, 0.f);
    float  l0 = 0.f, l1 = 0.f;
    if (lane < RPW) {
        int r = min(row0 + lane, M - 1);
        lrow = __ldg(locs2 + r);
        mrow = __ldg(meta4 + r);
        l0 = __ldg(loc);
        l1 = __ldg(loc + 1);
    }

    const float4* __restrict__ rp0 = feats4 + (size_t)row0 * (DIMS / 4);
    const float4* __restrict__ rp1 = has1 ? (rp0 + (DIMS / 4))     : rp0;
    const float4* __restrict__ rp2 = has2 ? (rp0 + 2 * (DIMS / 4)) : rp0;

    // Batch all 18 row loads up-front (MLP=18/warp), streaming (read-once).
    float4 a0 = __ldcs(rp0 + lane + 32 * 0);
    float4 a1 = __ldcs(rp0 + lane + 32 * 1);
    float4 a2 = __ldcs(rp0 + lane + 32 * 2);
    float4 a3 = __ldcs(rp0 + lane + 32 * 3);
    float4 a4 = __ldcs(rp0 + lane + 32 * 4);
    float4 a5 = __ldcs(rp0 + lane + 32 * 5);
    float4 c0 = __ldcs(rp1 + lane + 32 * 0);
    float4 c1 = __ldcs(rp1 + lane + 32 * 1);
    float4 c2 = __ldcs(rp1 + lane + 32 * 2);
    float4 c3 = __ldcs(rp1 + lane + 32 * 3);
    float4 c4 = __ldcs(rp1 + lane + 32 * 4);
    float4 c5 = __ldcs(rp1 + lane + 32 * 5);
    float4 d0 = __ldcs(rp2 + lane + 32 * 0);
    float4 d1 = __ldcs(rp2 + lane + 32 * 1);
    float4 d2 = __ldcs(rp2 + lane + 32 * 2);
    float4 d3 = __ldcs(rp2 + lane + 32 * 3);
    float4 d4 = __ldcs(rp2 + lane + 32 * 4);
    float4 d5 = __ldcs(rp2 + lane + 32 * 5);

    float dot0 = 0.f, ss0 = 0.f, dot1 = 0.f, ss1 = 0.f, dot2 = 0.f, ss2 = 0.f, qq = 0.f;
    {
        float4 b;
        b = __ldg(q4 + lane + 32 * 0);
        qq   += b.x*b.x + b.y*b.y + b.z*b.z + b.w*b.w;
        dot0 += a0.x*b.x + a0.y*b.y + a0.z*b.z + a0.w*b.w;
        ss0  += a0.x*a0.x + a0.y*a0.y + a0.z*a0.z + a0.w*a0.w;
        dot1 += c0.x*b.x + c0.y*b.y + c0.z*b.z + c0.w*b.w;
        ss1  += c0.x*c0.x + c0.y*c0.y + c0.z*c0.z + c0.w*c0.w;
        dot2 += d0.x*b.x + d0.y*b.y + d0.z*b.z + d0.w*b.w;
        ss2  += d0.x*d0.x + d0.y*d0.y + d0.z*d0.z + d0.w*d0.w;
        b = __ldg(q4 + lane + 32 * 1);
        qq   += b.x*b.x + b.y*b.y + b.z*b.z + b.w*b.w;
        dot0 += a1.x*b.x + a1.y*b.y + a1.z*b.z + a1.w*b.w;
        ss0  += a1.x*a1.x + a1.y*a1.y + a1.z*a1.z + a1.w*a1.w;
        dot1 += c1.x*b.x + c1.y*b.y + c1.z*b.z + c1.w*b.w;
        ss1  += c1.x*c1.x + c1.y*c1.y + c1.z*c1.z + c1.w*c1.w;
        dot2 += d1.x*b.x + d1.y*b.y + d1.z*b.z + d1.w*b.w;
        ss2  += d1.x*d1.x + d1.y*d1.y + d1.z*d1.z + d1.w*d1.w;
        b = __ldg(q4 + lane + 32 * 2);
        qq   += b.x*b.x + b.y*b.y + b.z*b.z + b.w*b.w;
        dot0 += a2.x*b.x + a2.y*b.y + a2.z*b.z + a2.w*b.w;
        ss0  += a2.x*a2.x + a2.y*a2.y + a2.z*a2.z + a2.w*a2.w;
        dot1 += c2.x*b.x + c2.y*b.y + c2.z*b.z + c2.w*b.w;
        ss1  += c2.x*c2.x + c2.y*c2.y + c2.z*c2.z + c2.w*c2.w;
        dot2 += d2.x*b.x + d2.y*b.y + d2.z*b.z + d2.w*b.w;
        ss2  += d2.x*d2.x + d2.y*d2.y + d2.z*d2.z + d2.w*d2.w;
        b = __ldg(q4 + lane + 32 * 3);
        qq   += b.x*b.x + b.y*b.y + b.z*b.z + b.w*b.w;
        dot0 += a3.x*b.x + a3.y*b.y + a3.z*b.z + a3.w*b.w;
        ss0  += a3.x*a3.x + a3.y*a3.y + a3.z*a3.z + a3.w*a3.w;
        dot1 += c3.x*b.x + c3.y*b.y + c3.z*b.z + c3.w*b.w;
        ss1  += c3.x*c3.x + c3.y*c3.y + c3.z*c3.z + c3.w*c3.w;
        dot2 += d3.x*b.x + d3.y*b.y + d3.z*b.z + d3.w*b.w;
        ss2  += d3.x*d3.x + d3.y*d3.y + d3.z*d3.z + d3.w*d3.w;
        b = __ldg(q4 + lane + 32 * 4);
        qq   += b.x*b.x + b.y*b.y + b.z*b.z + b.w*b.w;
        dot0 += a4.x*b.x + a4.y*b.y + a4.z*b.z + a4.w*b.w;
        ss0  += a4.x*a4.x + a4.y*a4.y + a4.z*a4.z + a4.w*a4.w;
        dot1 += c4.x*b.x + c4.y*b.y + c4.z*b.z + c4.w*b.w;
        ss1  += c4.x*c4.x + c4.y*c4.y + c4.z*c4.z + c4.w*c4.w;
        dot2 += d4.x*b.x + d4.y*b.y + d4.z*b.z + d4.w*b.w;
        ss2  += d4.x*d4.x + d4.y*d4.y + d4.z*d4.z + d4.w*d4.w;
        b = __ldg(q4 + lane + 32 * 5);
        qq   += b.x*b.x + b.y*b.y + b.z*b.z + b.w*b.w;
        dot0 += a5.x*b.x + a5.y*b.y + a5.z*b.z + a5.w*b.w;
        ss0  += a5.x*a5.x + a5.y*a5.y + a5.z*a5.z + a5.w*a5.w;
        dot1 += c5.x*b.x + c5.y*b.y + c5.z*b.z + c5.w*b.w;
        ss1  += c5.x*c5.x + c5.y*c5.y + c5.z*c5.z + c5.w*c5.w;
        dot2 += d5.x*b.x + d5.y*b.y + d5.z*b.z + d5.w*b.w;
        ss2  += d5.x*d5.x + d5.y*d5.y + d5.z*d5.z + d5.w*d5.w;
    }

    #pragma unroll
    for (int o = 16; o; o >>= 1) {
        dot0 += __shfl_xor_sync(0xffffffffu, dot0, o);
        ss0  += __shfl_xor_sync(0xffffffffu, ss0,  o);
        dot1 += __shfl_xor_sync(0xffffffffu, dot1, o);
        ss1  += __shfl_xor_sync(0xffffffffu, ss1,  o);
        dot2 += __shfl_xor_sync(0xffffffffu, dot2, o);
        ss2  += __shfl_xor_sync(0xffffffffu, ss2,  o);
        qq   += __shfl_xor_sync(0xffffffffu, qq,   o);
    }

    // Parallel epilogues: lane i finishes row0+i.
    const bool active = (lane == 0) || (lane == 1 && has1) || (lane == 2 && has2);
    if (active) {
        const float dot = (lane == 0) ? dot0 : (lane == 1 ? dot1 : dot2);
        const float ss  = (lane == 0) ? ss0  : (lane == 1 ? ss1  : ss2);
        const int   r   = row0 + lane;

        float qn = fmaxf(sqrtf(qq), EPSV);
        float mn = fmaxf(sqrtf(ss), EPSV);
        float sim = dot / (mn * qn);

        float dx = lrow.x - l0;
        float dy = lrow.y - l1;
        float spatial = 1.f / (1.f + sqrtf(dx * dx + dy * dy));

        // exp(-(3600 - ts)/3600) == exp(ts/3600 - 1)
        float temporal = expf(mrow.y * (1.f / 3600.f) - 1.f);

        g_scores[r] = (0.5f * sim + 0.3f * spatial + 0.2f * temporal) * mrow.x;
    }
}

// ---------------------------------------------------------------------------
// Kernel 2: top-k — R8's measured-best tail (12.0us): register phase-1 lists,
// shared-memory selection passes for the merges, last-block final merge.
// ---------------------------------------------------------------------------
template<int K>
__global__ void __launch_bounds__(TPB)
topk_tail(int M, float* __restrict__ out)
{
    __shared__ float s_val[TPB * K];
    __shared__ int   s_idx[TPB * K];
    __shared__ float s_rv[WPB];
    __shared__ int   s_ri[WPB];
    __shared__ int   s_rp[WPB];
    __shared__ bool  s_last;

    const int wid  = threadIdx.x >> 5;
    const int lane = threadIdx.x & 31;

    // ---- phase 1: per-thread register top-K (<=1 float4 per thread) ----
    float lv[K];
    int   li[K];
    #pragma unroll
    for (int j = 0; j < K; j++) { lv[j] = -INFINITY; li[j] = INT_MAX; }

    const float4* sc4 = (const float4*)g_scores;
    const int n4 = M >> 2;
    for (int i = blockIdx.x * TPB + threadIdx.x; i < n4; i += NBLK_T * TPB) {
        float4 v = sc4[i];
        const int base = 4 * i;
        insertK<K>(lv, li, v.x, base + 0);
        insertK<K>(lv, li, v.y, base + 1);
        insertK<K>(lv, li, v.z, base + 2);
        insertK<K>(lv, li, v.w, base + 3);
    }
    if (blockIdx.x == 0) {                     // M % 4 remainder
        int i = (n4 << 2) + threadIdx.x;
        if (i < M) insertK<K>(lv, li, g_scores[i], i);
    }

    #pragma unroll
    for (int j = 0; j < K; j++) {
        s_val[threadIdx.x * K + j] = lv[j];
        s_idx[threadIdx.x * K + j] = li[j];
    }
    __syncthreads();

    // ---- phase 2: block merge via K selection passes, write candidates ----
    const int total = TPB * K;
    #pragma unroll 1
    for (int sel = 0; sel < K; sel++) {
        float bv = -INFINITY; int bi = INT_MAX; int bp = -1;
        for (int p = threadIdx.x; p < total; p += TPB) {
            if (better(s_val[p], s_idx[p], bv, bi)) { bv = s_val[p]; bi = s_idx[p]; bp = p; }
        }
        #pragma unroll
        for (int o = 16; o; o >>= 1) {
            float ov = __shfl_xor_sync(0xffffffffu, bv, o);
            int   oi = __shfl_xor_sync(0xffffffffu, bi, o);
            int   op = __shfl_xor_sync(0xffffffffu, bp, o);
            if (better(ov, oi, bv, bi)) { bv = ov; bi = oi; bp = op; }
        }
        if (lane == 0) { s_rv[wid] = bv; s_ri[wid] = bi; s_rp[wid] = bp; }
        __syncthreads();
        if (threadIdx.x == 0) {
            bv = s_rv[0]; bi = s_ri[0]; bp = s_rp[0];
            #pragma unroll
            for (int w = 1; w < WPB; w++)
                if (better(s_rv[w], s_ri[w], bv, bi)) { bv = s_rv[w]; bi = s_ri[w]; bp = s_rp[w]; }
            g_cand_val[blockIdx.x * K + sel] = bv;
            g_cand_idx[blockIdx.x * K + sel] = bi;
            if (bp >= 0) { s_val[bp] = -INFINITY; s_idx[bp] = INT_MAX; }
        }
        __syncthreads();
    }

    // ---- phase 3: last block merges all candidates ----
    if (threadIdx.x == 0) {
        __threadfence();                       // publish this block's candidates
        unsigned int t = atomicAdd(&g_done, 1u);
        s_last = (t == (unsigned int)(gridDim.x - 1));
    }
    __syncthreads();
    if (!s_last) return;
    __threadfence();

    const int ncand = NBLK_T * K;
    #pragma unroll
    for (int j = 0; j < K; j++) { lv[j] = -INFINITY; li[j] = INT_MAX; }
    for (int p = threadIdx.x; p < ncand; p += TPB)
        insertK<K>(lv, li, __ldcg(&g_cand_val[p]), __ldcg(&g_cand_idx[p]));

    #pragma unroll
    for (int j = 0; j < K; j++) {
        s_val[threadIdx.x * K + j] = lv[j];
        s_idx[threadIdx.x * K + j] = li[j];
    }
    __syncthreads();

    #pragma unroll 1
    for (int sel = 0; sel < K; sel++) {
        float bv = -INFINITY; int bi = INT_MAX; int bp = -1;
        for (int p = threadIdx.x; p < total; p += TPB) {
            if (better(s_val[p], s_idx[p], bv, bi)) { bv = s_val[p]; bi = s_idx[p]; bp = p; }
        }
        #pragma unroll
        for (int o = 16; o; o >>= 1) {
            float ov = __shfl_xor_sync(0xffffffffu, bv, o);
            int   oi = __shfl_xor_sync(0xffffffffu, bi, o);
            int   op = __shfl_xor_sync(0xffffffffu, bp, o);
            if (better(ov, oi, bv, bi)) { bv = ov; bi = oi; bp = op; }
        }
        if (lane == 0) { s_rv[wid] = bv; s_ri[wid] = bi; s_rp[wid] = bp; }
        __syncthreads();
        if (threadIdx.x == 0) {
            bv = s_rv[0]; bi = s_ri[0]; bp = s_rp[0];
            #pragma unroll
            for (int w = 1; w < WPB; w++)
                if (better(s_rv[w], s_ri[w], bv, bi)) { bv = s_rv[w]; bi = s_ri[w]; bp = s_rp[w]; }
            out[sel]     = bv;              // top_scores
            out[K + sel] = (float)bi;       // top_indices (exact in fp32 for idx < 2^24)
            if (bp >= 0) { s_val[bp] = -INFINITY; s_idx[bp] = INT_MAX; }
        }
        __syncthreads();
    }

    if (threadIdx.x == 0) g_done = 0;          // reset for next graph replay
}

// ---------------------------------------------------------------------------
// Launch
// ---------------------------------------------------------------------------
extern "C" void kernel_launch(void* const* d_in, const int* in_sizes, int n_in,
                              void* d_out, int out_size)
{
    const float* q     = (const float*)d_in[0];   // (768,)
    const float* loc   = (const float*)d_in[1];   // (2,)
    const float* feats = (const float*)d_in[2];   // (M, 768)
    const float* locs  = (const float*)d_in[3];   // (M, 2)
    const float* meta  = (const float*)d_in[4];   // (M, 4)
    float* out = (float*)d_out;                   // [k scores | k indices]

    int M = in_sizes[2] / DIMS;
    if (M > MAXM) M = MAXM;
    int k = out_size / 2;
    if (k < 1) k = 1;
    if (k > KMAX) k = KMAX;

    const int nwarp = (M + RPW - 1) / RPW;
    const int nblk_score = (nwarp + WPB - 1) / WPB;

    score_kernel<<<nblk_score, TPB>>>((const float4*)q, loc,
                                      (const float4*)feats,
                                      (const float2*)locs,
                                      (const float4*)meta, M);

    switch (k) {
        case 1: topk_tail<1><<<NBLK_T, TPB>>>(M, out); break;
        case 2: topk_tail<2><<<NBLK_T, TPB>>>(M, out); break;
        case 3: topk_tail<3><<<NBLK_T, TPB>>>(M, out); break;
        case 4: topk_tail<4><<<NBLK_T, TPB>>>(M, out); break;
        case 5: topk_tail<5><<<NBLK_T, TPB>>>(M, out); break;
        case 6: topk_tail<6><<<NBLK_T, TPB>>>(M, out); break;
        case 7: topk_tail<7><<<NBLK_T, TPB>>>(M, out); break;
        default: topk_tail<8><<<NBLK_T, TPB>>>(M, out); break;
    }
}